// round 13
// baseline (speedup 1.0000x reference)
#include <cuda_runtime.h>
#include <math.h>
#include <float.h>

#define Bq   1024
#define Dd   1024
#define Nn   65536
#define Mm   8
#define KS   256
#define DSs  128
#define OUTn 2048
#define KTOP 64

// ---------------- static device scratch (no dynamic allocation) ----------------
__device__ float g_qa[Bq * Dd];                // 4 MB : q = x @ W
__device__ float g_lut[Bq * Mm * KS];          // 8 MB : lut[b][m][c] = c_sq - 2*cross
__device__ float g_csq[Mm * KS];               // 8 KB
__device__ unsigned long long g_codes[Nn];     // 512 KB : 8 packed u8 codes per n

// ---------------- K0: pack key_codes (N x 8 int32) -> u64 per n ----------------
__global__ void pack_codes_k(const int* __restrict__ kc) {
    int n = blockIdx.x * blockDim.x + threadIdx.x;   // grid exactly N
    unsigned long long v = 0;
#pragma unroll
    for (int m = 0; m < 8; m++)
        v |= (unsigned long long)((unsigned)kc[n * 8 + m] & 255u) << (8 * m);
    g_codes[n] = v;
}

// ---------------- K0b: c_sq[m][c] = ||codebook[m][c]||^2 ----------------
__global__ void csq_k(const float* __restrict__ cb) {
    int g = blockIdx.x * blockDim.x + threadIdx.x;   // 2048 warps exactly
    int w = g >> 5, lane = g & 31;
    const float* r = cb + w * DSs;
    float s = 0.f;
#pragma unroll
    for (int d = lane; d < DSs; d += 32) { float x = r[d]; s = fmaf(x, x, s); }
#pragma unroll
    for (int o = 16; o; o >>= 1) s += __shfl_xor_sync(0xffffffffu, s, o);
    if (lane == 0) g_csq[w] = s;
}

// ================= K1: q = x @ W via 3xTF32 tensor-core mma =================
__device__ __forceinline__ unsigned f2tf(float x) {
    unsigned r;
    asm("cvt.rna.tf32.f32 %0, %1;" : "=r"(r) : "f"(x));
    return r;
}

#define MMA_TF32(c, a, b0v, b1v)                                             \
    asm volatile("mma.sync.aligned.m16n8k8.row.col.f32.tf32.tf32.f32 "       \
        "{%0,%1,%2,%3}, {%4,%5,%6,%7}, {%8,%9}, {%0,%1,%2,%3};"              \
        : "+f"((c)[0]), "+f"((c)[1]), "+f"((c)[2]), "+f"((c)[3])             \
        : "r"((a)[0]), "r"((a)[1]), "r"((a)[2]), "r"((a)[3]),                \
          "r"(b0v), "r"(b1v))

#define A_STRIDE 20
#define B_STRIDE 72

__global__ void __launch_bounds__(128) gemm_tc(const float* __restrict__ A,
                                               const float* __restrict__ W) {
    __shared__ unsigned Ah[64 * A_STRIDE], Al[64 * A_STRIDE];   // [m][k] pad 20
    __shared__ unsigned Bh[16 * B_STRIDE], Bl[16 * B_STRIDE];   // [k][n] pad 72
    int tid  = threadIdx.x;
    int lane = tid & 31;
    int w    = tid >> 5;
    int m0 = blockIdx.y * 64;
    int n0 = blockIdx.x * 64;
    int wm = (w & 1) * 32;          // warp tile 32x32
    int wn = (w >> 1) * 32;

    float c[2][4][4];
#pragma unroll
    for (int mt = 0; mt < 2; mt++)
#pragma unroll
        for (int nt = 0; nt < 4; nt++)
#pragma unroll
            for (int r = 0; r < 4; r++) c[mt][nt][r] = 0.f;

    int ar = tid >> 2, aq = (tid & 3) * 4;     // A: 32 rows/pass, 4 k-floats
    int br = tid >> 4, bq = (tid & 15) * 4;    // B: 8 rows/pass, 4 n-floats

    // prefetch k0 = 0
    float4 vA[2], vB[2];
#pragma unroll
    for (int p = 0; p < 2; p++) {
        vA[p] = *(const float4*)&A[(m0 + ar + p * 32) * Dd + aq];
        vB[p] = *(const float4*)&W[(br + p * 8) * Dd + n0 + bq];
    }

    for (int k0 = 0; k0 < Dd; k0 += 16) {
        // prefetch next k slice while converting/storing this one
        float4 nA[2], nB[2];
        if (k0 + 16 < Dd) {
#pragma unroll
            for (int p = 0; p < 2; p++) {
                nA[p] = *(const float4*)&A[(m0 + ar + p * 32) * Dd + k0 + 16 + aq];
                nB[p] = *(const float4*)&W[(k0 + 16 + br + p * 8) * Dd + n0 + bq];
            }
        }
#pragma unroll
        for (int p = 0; p < 2; p++) {
            float4 v = vA[p];
            unsigned h0 = f2tf(v.x), h1 = f2tf(v.y), h2 = f2tf(v.z), h3 = f2tf(v.w);
            unsigned l0 = f2tf(v.x - __uint_as_float(h0));
            unsigned l1 = f2tf(v.y - __uint_as_float(h1));
            unsigned l2 = f2tf(v.z - __uint_as_float(h2));
            unsigned l3 = f2tf(v.w - __uint_as_float(h3));
            int base = (ar + p * 32) * A_STRIDE + aq;
            Ah[base + 0] = h0; Ah[base + 1] = h1; Ah[base + 2] = h2; Ah[base + 3] = h3;
            Al[base + 0] = l0; Al[base + 1] = l1; Al[base + 2] = l2; Al[base + 3] = l3;
        }
#pragma unroll
        for (int p = 0; p < 2; p++) {
            float4 v = vB[p];
            unsigned h0 = f2tf(v.x), h1 = f2tf(v.y), h2 = f2tf(v.z), h3 = f2tf(v.w);
            unsigned l0 = f2tf(v.x - __uint_as_float(h0));
            unsigned l1 = f2tf(v.y - __uint_as_float(h1));
            unsigned l2 = f2tf(v.z - __uint_as_float(h2));
            unsigned l3 = f2tf(v.w - __uint_as_float(h3));
            int base = (br + p * 8) * B_STRIDE + bq;
            Bh[base + 0] = h0; Bh[base + 1] = h1; Bh[base + 2] = h2; Bh[base + 3] = h3;
            Bl[base + 0] = l0; Bl[base + 1] = l1; Bl[base + 2] = l2; Bl[base + 3] = l3;
        }
        __syncthreads();

#pragma unroll
        for (int ks = 0; ks < 2; ks++) {
            int kb = ks * 8;
            unsigned ah[2][4], al[2][4];
#pragma unroll
            for (int mt = 0; mt < 2; mt++) {
                int r0 = wm + mt * 16 + (lane >> 2);
                int k  = kb + (lane & 3);
                ah[mt][0] = Ah[ r0      * A_STRIDE + k    ];
                ah[mt][1] = Ah[(r0 + 8) * A_STRIDE + k    ];
                ah[mt][2] = Ah[ r0      * A_STRIDE + k + 4];
                ah[mt][3] = Ah[(r0 + 8) * A_STRIDE + k + 4];
                al[mt][0] = Al[ r0      * A_STRIDE + k    ];
                al[mt][1] = Al[(r0 + 8) * A_STRIDE + k    ];
                al[mt][2] = Al[ r0      * A_STRIDE + k + 4];
                al[mt][3] = Al[(r0 + 8) * A_STRIDE + k + 4];
            }
#pragma unroll
            for (int nt = 0; nt < 4; nt++) {
                int cb = wn + nt * 8 + (lane >> 2);
                int kr = kb + (lane & 3);
                unsigned bh0 = Bh[ kr      * B_STRIDE + cb];
                unsigned bh1 = Bh[(kr + 4) * B_STRIDE + cb];
                unsigned bl0 = Bl[ kr      * B_STRIDE + cb];
                unsigned bl1 = Bl[(kr + 4) * B_STRIDE + cb];
#pragma unroll
                for (int mt = 0; mt < 2; mt++) {
                    MMA_TF32(c[mt][nt], ah[mt], bh0, bh1);   // hi*hi
                    MMA_TF32(c[mt][nt], ah[mt], bl0, bl1);   // hi*lo
                    MMA_TF32(c[mt][nt], al[mt], bh0, bh1);   // lo*hi
                }
            }
        }
        __syncthreads();
#pragma unroll
        for (int p = 0; p < 2; p++) { vA[p] = nA[p]; vB[p] = nB[p]; }
    }

    // epilogue: D m16n8 layout -> g_qa
#pragma unroll
    for (int mt = 0; mt < 2; mt++)
#pragma unroll
        for (int nt = 0; nt < 4; nt++) {
            int row = m0 + wm + mt * 16 + (lane >> 2);
            int col = n0 + wn + nt * 8 + (lane & 3) * 2;
            *(float2*)&g_qa[row * Dd + col]       = make_float2(c[mt][nt][0], c[mt][nt][1]);
            *(float2*)&g_qa[(row + 8) * Dd + col] = make_float2(c[mt][nt][2], c[mt][nt][3]);
        }
}

// ---------------- K2: lut[b][m][c] = csq[m][c] - 2 * dot(q[b][m*128:], cb[m][c]) ----------------
__global__ void __launch_bounds__(256) lut_k(const float* __restrict__ cb) {
    int m  = blockIdx.z;
    int b0 = blockIdx.y * 64;
    int c0 = blockIdx.x * 64;
    __shared__ float Qs[32][64];   // [d][b]
    __shared__ float Cs[32][64];   // [d][c]
    int tid = threadIdx.x;
    int tx = tid & 15, ty = tid >> 4;
    float acc[4][4];
#pragma unroll
    for (int i = 0; i < 4; i++)
#pragma unroll
        for (int j = 0; j < 4; j++) acc[i][j] = 0.f;

    const float* cbm = cb + m * KS * DSs;
    for (int k0 = 0; k0 < DSs; k0 += 32) {
#pragma unroll
        for (int p = 0; p < 2; p++) {
            int l = (p * 256 + tid) * 4;
            int r = l >> 5, c = l & 31;
            int qi = (b0 + r) * Dd + m * DSs + k0 + c;
            float4 va = *(const float4*)&g_qa[qi];
            Qs[c + 0][r] = va.x; Qs[c + 1][r] = va.y;
            Qs[c + 2][r] = va.z; Qs[c + 3][r] = va.w;
            float4 u = *(const float4*)&cbm[(c0 + r) * DSs + k0 + c];
            Cs[c + 0][r] = u.x; Cs[c + 1][r] = u.y;
            Cs[c + 2][r] = u.z; Cs[c + 3][r] = u.w;
        }
        __syncthreads();
#pragma unroll
        for (int kk = 0; kk < 32; kk++) {
            float ra[4], rb[4];
            *(float4*)&ra[0] = *(float4*)&Qs[kk][ty * 4];
            *(float4*)&rb[0] = *(float4*)&Cs[kk][tx * 4];
#pragma unroll
            for (int i = 0; i < 4; i++)
#pragma unroll
                for (int j = 0; j < 4; j++) acc[i][j] = fmaf(ra[i], rb[j], acc[i][j]);
        }
        __syncthreads();
    }
#pragma unroll
    for (int i = 0; i < 4; i++) {
        int bb = b0 + ty * 4 + i;
        int cc = c0 + tx * 4;
        float4 s4 = *(const float4*)&g_csq[m * KS + cc];
        float4 v = make_float4(s4.x - 2.f * acc[i][0],
                               s4.y - 2.f * acc[i][1],
                               s4.z - 2.f * acc[i][2],
                               s4.w - 2.f * acc[i][3]);
        *(float4*)&g_lut[bb * OUTn + m * KS + cc] = v;
    }
}

// ================= register/shfl bitonic top-64 machinery =================
__device__ __forceinline__ void cx_shfl(float& v, int& i, int lane, int ehi, int k, int j) {
    float pv = __shfl_xor_sync(0xffffffffu, v, j);
    int   pi = __shfl_xor_sync(0xffffffffu, i, j);
    bool up = (((ehi + lane) & k) == 0);
    bool keep_min = (up == ((lane & j) == 0));
    if ((pv < v) == keep_min) { v = pv; i = pi; }
}

// full bitonic sort of 64 (ascending)
__device__ __forceinline__ void sort64(float& v0, int& i0, float& v1, int& i1, int lane) {
#pragma unroll
    for (int k = 2; k <= 32; k <<= 1) {
#pragma unroll
        for (int j = k >> 1; j >= 1; j >>= 1) {
            cx_shfl(v0, i0, lane, 0, k, j);
            cx_shfl(v1, i1, lane, 32, k, j);
        }
    }
    if (v1 < v0) { float t = v0; v0 = v1; v1 = t; int ti = i0; i0 = i1; i1 = ti; }
#pragma unroll
    for (int j = 16; j >= 1; j >>= 1) {
        cx_shfl(v0, i0, lane, 0, 64, j);
        cx_shfl(v1, i1, lane, 32, 64, j);
    }
}

// merge kept(asc) with batch(asc): kept <- smallest 64 of union, sorted ascending
__device__ __forceinline__ void merge64(float& k0v, int& k0i, float& k1v, int& k1i,
                                        float b0v, int b0i, float b1v, int b1i, int lane) {
    float r0v = __shfl_xor_sync(0xffffffffu, b1v, 31);
    int   r0i = __shfl_xor_sync(0xffffffffu, b1i, 31);
    float r1v = __shfl_xor_sync(0xffffffffu, b0v, 31);
    int   r1i = __shfl_xor_sync(0xffffffffu, b0i, 31);
    if (r0v < k0v) { k0v = r0v; k0i = r0i; }
    if (r1v < k1v) { k1v = r1v; k1i = r1i; }
    if (k1v < k0v) { float t = k0v; k0v = k1v; k1v = t; int ti = k0i; k0i = k1i; k1i = ti; }
#pragma unroll
    for (int j = 16; j >= 1; j >>= 1) {
        cx_shfl(k0v, k0i, lane, 0, 64, j);
        cx_shfl(k1v, k1i, lane, 32, 64, j);
    }
}

#define WBUF 128   // per-warp candidate buffer slots

// ---------------- K3: warp-autonomous PQ scan, 2 codes/lane/iter ----------------
__global__ void __launch_bounds__(512, 4) scan_k(const int* __restrict__ vcodes,
                                                 const float* __restrict__ vcb,
                                                 const float* __restrict__ bias,
                                                 float* __restrict__ out) {
    int b = blockIdx.x;
    int tid = threadIdx.x;
    int lane = tid & 31;
    int w = tid >> 5;                  // 16 warps
    __shared__ float lut_s[2048];      // 8 KB
    __shared__ float bufd[16 * WBUF];  // 8 KB : per-warp candidate buffer / kept lists
    __shared__ int   bufi[16 * WBUF];  // 8 KB
    __shared__ float s_w[KTOP];
    __shared__ float s_winv;

    // stage LUT (8 KB)
    ((float4*)lut_s)[tid] = ((const float4*)&g_lut[b * 2048])[tid];
    __syncthreads();

    float* mbd = bufd + w * WBUF;
    int*   mbi = bufi + w * WBUF;
    int   cnt = 0;
    float tau = FLT_MAX;
    float k0v = FLT_MAX, k1v = FLT_MAX;   // kept top-64 (registers, sorted asc)
    int   k0i = 0, k1i = 0;
    unsigned lanemask_lt = (1u << lane) - 1u;

    int nbase = w << 12;               // warp stripe: 4096 codes
    const uint4* cp = (const uint4*)g_codes;    // element i = codes {2i, 2i+1}
    int ibase = (nbase >> 1) + lane;
    uint4 c = cp[ibase];
#pragma unroll 1
    for (int it = 0; it < 64; ++it) {
        uint4 nx = (it < 63) ? cp[ibase + (it + 1) * 32] : make_uint4(0, 0, 0, 0);
        int n0 = nbase + (it << 6) + (lane << 1);
        // code 0 : (c.x, c.y)
        float a0 = lut_s[          (c.x         & 255u)];
        float a1 = lut_s[ 256 + ((c.x >>  8) & 255u)];
        float a2 = lut_s[ 512 + ((c.x >> 16) & 255u)];
        float a3 = lut_s[ 768 +  (c.x >> 24)         ];
        float a4 = lut_s[1024 + ( c.y         & 255u)];
        float a5 = lut_s[1280 + ((c.y >>  8) & 255u)];
        float a6 = lut_s[1536 + ((c.y >> 16) & 255u)];
        float a7 = lut_s[1792 +  (c.y >> 24)         ];
        // code 1 : (c.z, c.w)
        float e0 = lut_s[          (c.z         & 255u)];
        float e1 = lut_s[ 256 + ((c.z >>  8) & 255u)];
        float e2 = lut_s[ 512 + ((c.z >> 16) & 255u)];
        float e3 = lut_s[ 768 +  (c.z >> 24)         ];
        float e4 = lut_s[1024 + ( c.w         & 255u)];
        float e5 = lut_s[1280 + ((c.w >>  8) & 255u)];
        float e6 = lut_s[1536 + ((c.w >> 16) & 255u)];
        float e7 = lut_s[1792 +  (c.w >> 24)         ];
        float dA = ((a0 + a1) + (a2 + a3)) + ((a4 + a5) + (a6 + a7));
        float dB = ((e0 + e1) + (e2 + e3)) + ((e4 + e5) + (e6 + e7));
        c = nx;
        unsigned b0 = __ballot_sync(0xffffffffu, dA < tau);
        unsigned b1 = __ballot_sync(0xffffffffu, dB < tau);
        int c0 = __popc(b0);
        if (dA < tau) {
            int pos = cnt + __popc(b0 & lanemask_lt);
            mbd[pos] = dA; mbi[pos] = n0;
        }
        if (dB < tau) {
            int pos = cnt + c0 + __popc(b1 & lanemask_lt);
            mbd[pos] = dB; mbi[pos] = n0 + 1;
        }
        cnt += c0 + __popc(b1);
        if (cnt >= 64) {                    // flush: sort batch of 64, merge into kept
            __syncwarp();
            float b0v = mbd[lane], b1v = mbd[32 + lane];
            int   b0i = mbi[lane], b1i = mbi[32 + lane];
            int left = cnt - 64;
            for (int i2 = lane; i2 < left; i2 += 32) {
                mbd[i2] = mbd[64 + i2]; mbi[i2] = mbi[64 + i2];
            }
            cnt = left;
            __syncwarp();
            sort64(b0v, b0i, b1v, b1i, lane);
            merge64(k0v, k0i, k1v, k1i, b0v, b0i, b1v, b1i, lane);
            tau = __shfl_sync(0xffffffffu, k1v, 31);
        }
    }
    // final partial flush
    if (cnt > 0) {
        for (int i2 = cnt + lane; i2 < 64; i2 += 32) mbd[i2] = FLT_MAX;
        __syncwarp();
        float b0v = mbd[lane], b1v = mbd[32 + lane];
        int   b0i = mbi[lane], b1i = mbi[32 + lane];
        sort64(b0v, b0i, b1v, b1i, lane);
        merge64(k0v, k0i, k1v, k1i, b0v, b0i, b1v, b1i, lane);
    }
    // publish warp's sorted top-64
    mbd[lane] = k0v;  mbd[32 + lane] = k1v;
    mbi[lane] = k0i;  mbi[32 + lane] = k1i;
    __syncthreads();

    // tournament merge of 16 sorted lists (4 rounds, register merges)
#pragma unroll
    for (int step = 1; step < 16; step <<= 1) {
        if (w * 2 * step < 16) {
            int ia = w * 2 * step, ib = ia + step;
            float a0 = bufd[ia * WBUF + lane],      a1 = bufd[ia * WBUF + 32 + lane];
            int   x0 = bufi[ia * WBUF + lane],      x1 = bufi[ia * WBUF + 32 + lane];
            float c0 = bufd[ib * WBUF + lane],      c1 = bufd[ib * WBUF + 32 + lane];
            int   y0 = bufi[ib * WBUF + lane],      y1 = bufi[ib * WBUF + 32 + lane];
            merge64(a0, x0, a1, x1, c0, y0, c1, y1, lane);
            bufd[ia * WBUF + lane] = a0;  bufd[ia * WBUF + 32 + lane] = a1;
            bufi[ia * WBUF + lane] = x0;  bufi[ia * WBUF + 32 + lane] = x1;
        }
        __syncthreads();
    }
    // final top-64 sorted ascending at bufd[0..63] / bufi[0..63]

    // softmax over -dist (q_sq shift cancels; shift by best dist)
    float d0 = bufd[0];
    if (tid < KTOP) s_w[tid] = expf(d0 - bufd[tid]);
    __syncthreads();
    if (tid == 0) {
        float s = 0.f;
        for (int i = 0; i < KTOP; i++) s += s_w[i];
        s_winv = 1.0f / s;
    }
    __syncthreads();

    // y[b, o] = bias[o] + sum_k w_k * vcb[mv][value_codes[n_k][mv]][dv]
    int o0   = tid << 2;          // 4 outputs per thread (512*4 = 2048)
    int mv   = tid >> 6;          // warp-uniform
    int col4 = (o0 & 255) >> 2;
    float4 acc = *(const float4*)&bias[o0];
    const float4* vcb4 = (const float4*)vcb;
    float winv = s_winv;
#pragma unroll 4
    for (int kk = 0; kk < KTOP; kk++) {
        int n = bufi[kk];
        float wt = s_w[kk] * winv;
        int code = vcodes[n * 8 + mv];
        float4 v = vcb4[(((mv << 8) + code) << 6) + col4];
        acc.x = fmaf(wt, v.x, acc.x);
        acc.y = fmaf(wt, v.y, acc.y);
        acc.z = fmaf(wt, v.z, acc.z);
        acc.w = fmaf(wt, v.w, acc.w);
    }
    *(float4*)&out[b * OUTn + o0] = acc;
}

// ---------------- launch ----------------
extern "C" void kernel_launch(void* const* d_in, const int* in_sizes, int n_in,
                              void* d_out, int out_size) {
    const float* x    = (const float*)d_in[0];   // (B, D)
    const float* W    = (const float*)d_in[1];   // (D, D)
    const float* kcb  = (const float*)d_in[2];   // (M, Ks, DS)
    const float* vcb  = (const float*)d_in[3];   // (MV, Ks, DV)
    const float* bias = (const float*)d_in[4];   // (OUT,)
    const int*   kc   = (const int*)d_in[5];     // (N, M)
    const int*   vc   = (const int*)d_in[6];     // (N, MV)
    float* out = (float*)d_out;                  // (B, OUT)

    pack_codes_k<<<Nn / 256, 256>>>(kc);
    csq_k<<<(Mm * KS * 32) / 256, 256>>>(kcb);
    gemm_tc<<<dim3(Dd / 64, Bq / 64), 128>>>(x, W);
    lut_k<<<dim3(KS / 64, Bq / 64, Mm), 256>>>(kcb);
    scan_k<<<Bq, 512>>>(vc, vcb, bias, out);
}

// round 14
// speedup vs baseline: 1.0564x; 1.0564x over previous
#include <cuda_runtime.h>
#include <math.h>
#include <float.h>

#define Bq   1024
#define Dd   1024
#define Nn   65536
#define Mm   8
#define KS   256
#define DSs  128
#define OUTn 2048
#define KTOP 64

// ---------------- static device scratch (no dynamic allocation) ----------------
__device__ float g_qa[Bq * Dd];                // 4 MB : q = x @ W
__device__ float g_lut[Bq * Mm * KS];          // 8 MB : lut[b][m][c] = c_sq - 2*cross
__device__ float g_csq[Mm * KS];               // 8 KB
__device__ unsigned long long g_codes[Nn];     // 512 KB : 8 packed u8 codes per n

// ---------------- K0: pack key_codes (N x 8 int32) -> u64 per n ----------------
__global__ void pack_codes_k(const int* __restrict__ kc) {
    int n = blockIdx.x * blockDim.x + threadIdx.x;   // grid exactly N
    unsigned long long v = 0;
#pragma unroll
    for (int m = 0; m < 8; m++)
        v |= (unsigned long long)((unsigned)kc[n * 8 + m] & 255u) << (8 * m);
    g_codes[n] = v;
}

// ---------------- K0b: c_sq[m][c] = ||codebook[m][c]||^2 ----------------
__global__ void csq_k(const float* __restrict__ cb) {
    int g = blockIdx.x * blockDim.x + threadIdx.x;   // 2048 warps exactly
    int w = g >> 5, lane = g & 31;
    const float* r = cb + w * DSs;
    float s = 0.f;
#pragma unroll
    for (int d = lane; d < DSs; d += 32) { float x = r[d]; s = fmaf(x, x, s); }
#pragma unroll
    for (int o = 16; o; o >>= 1) s += __shfl_xor_sync(0xffffffffu, s, o);
    if (lane == 0) g_csq[w] = s;
}

// ================= 3xTF32 tensor-core mma helpers =================
__device__ __forceinline__ unsigned f2tf(float x) {
    unsigned r;
    asm("cvt.rna.tf32.f32 %0, %1;" : "=r"(r) : "f"(x));
    return r;
}

#define MMA_TF32(c, a, b0v, b1v)                                             \
    asm volatile("mma.sync.aligned.m16n8k8.row.col.f32.tf32.tf32.f32 "       \
        "{%0,%1,%2,%3}, {%4,%5,%6,%7}, {%8,%9}, {%0,%1,%2,%3};"              \
        : "+f"((c)[0]), "+f"((c)[1]), "+f"((c)[2]), "+f"((c)[3])             \
        : "r"((a)[0]), "r"((a)[1]), "r"((a)[2]), "r"((a)[3]),                \
          "r"(b0v), "r"(b1v))

#define A_STRIDE 20
#define B_STRIDE 72

// ================= K1: q = x @ W via 3xTF32 mma (R11 version) =================
__global__ void __launch_bounds__(128) gemm_tc(const float* __restrict__ A,
                                               const float* __restrict__ W) {
    __shared__ unsigned Ah[64 * A_STRIDE], Al[64 * A_STRIDE];   // [m][k] pad 20
    __shared__ unsigned Bh[16 * B_STRIDE], Bl[16 * B_STRIDE];   // [k][n] pad 72
    int tid  = threadIdx.x;
    int lane = tid & 31;
    int w    = tid >> 5;
    int m0 = blockIdx.y * 64;
    int n0 = blockIdx.x * 64;
    int wm = (w & 1) * 32;          // warp tile 32x32
    int wn = (w >> 1) * 32;

    float c[2][4][4];
#pragma unroll
    for (int mt = 0; mt < 2; mt++)
#pragma unroll
        for (int nt = 0; nt < 4; nt++)
#pragma unroll
            for (int r = 0; r < 4; r++) c[mt][nt][r] = 0.f;

    int ar = tid >> 2, aq = (tid & 3) * 4;     // A: 32 rows/pass, 4 k-floats
    int br = tid >> 4, bq = (tid & 15) * 4;    // B: 8 rows/pass, 4 n-floats

    for (int k0 = 0; k0 < Dd; k0 += 16) {
#pragma unroll
        for (int p = 0; p < 2; p++) {
            int r = ar + p * 32;
            float4 v = *(const float4*)&A[(m0 + r) * Dd + k0 + aq];
            unsigned h0 = f2tf(v.x), h1 = f2tf(v.y), h2 = f2tf(v.z), h3 = f2tf(v.w);
            unsigned l0 = f2tf(v.x - __uint_as_float(h0));
            unsigned l1 = f2tf(v.y - __uint_as_float(h1));
            unsigned l2 = f2tf(v.z - __uint_as_float(h2));
            unsigned l3 = f2tf(v.w - __uint_as_float(h3));
            int base = r * A_STRIDE + aq;
            Ah[base + 0] = h0; Ah[base + 1] = h1; Ah[base + 2] = h2; Ah[base + 3] = h3;
            Al[base + 0] = l0; Al[base + 1] = l1; Al[base + 2] = l2; Al[base + 3] = l3;
        }
#pragma unroll
        for (int p = 0; p < 2; p++) {
            int r = br + p * 8;
            float4 v = *(const float4*)&W[(k0 + r) * Dd + n0 + bq];
            unsigned h0 = f2tf(v.x), h1 = f2tf(v.y), h2 = f2tf(v.z), h3 = f2tf(v.w);
            unsigned l0 = f2tf(v.x - __uint_as_float(h0));
            unsigned l1 = f2tf(v.y - __uint_as_float(h1));
            unsigned l2 = f2tf(v.z - __uint_as_float(h2));
            unsigned l3 = f2tf(v.w - __uint_as_float(h3));
            int base = r * B_STRIDE + bq;
            Bh[base + 0] = h0; Bh[base + 1] = h1; Bh[base + 2] = h2; Bh[base + 3] = h3;
            Bl[base + 0] = l0; Bl[base + 1] = l1; Bl[base + 2] = l2; Bl[base + 3] = l3;
        }
        __syncthreads();

#pragma unroll
        for (int ks = 0; ks < 2; ks++) {
            int kb = ks * 8;
            unsigned ah[2][4], al[2][4];
#pragma unroll
            for (int mt = 0; mt < 2; mt++) {
                int r0 = wm + mt * 16 + (lane >> 2);
                int k  = kb + (lane & 3);
                ah[mt][0] = Ah[ r0      * A_STRIDE + k    ];
                ah[mt][1] = Ah[(r0 + 8) * A_STRIDE + k    ];
                ah[mt][2] = Ah[ r0      * A_STRIDE + k + 4];
                ah[mt][3] = Ah[(r0 + 8) * A_STRIDE + k + 4];
                al[mt][0] = Al[ r0      * A_STRIDE + k    ];
                al[mt][1] = Al[(r0 + 8) * A_STRIDE + k    ];
                al[mt][2] = Al[ r0      * A_STRIDE + k + 4];
                al[mt][3] = Al[(r0 + 8) * A_STRIDE + k + 4];
            }
#pragma unroll
            for (int nt = 0; nt < 4; nt++) {
                int cb = wn + nt * 8 + (lane >> 2);
                int kr = kb + (lane & 3);
                unsigned bh0 = Bh[ kr      * B_STRIDE + cb];
                unsigned bh1 = Bh[(kr + 4) * B_STRIDE + cb];
                unsigned bl0 = Bl[ kr      * B_STRIDE + cb];
                unsigned bl1 = Bl[(kr + 4) * B_STRIDE + cb];
#pragma unroll
                for (int mt = 0; mt < 2; mt++) {
                    MMA_TF32(c[mt][nt], ah[mt], bh0, bh1);   // hi*hi
                    MMA_TF32(c[mt][nt], ah[mt], bl0, bl1);   // hi*lo
                    MMA_TF32(c[mt][nt], al[mt], bh0, bh1);   // lo*hi
                }
            }
        }
        __syncthreads();
    }

    // epilogue: D m16n8 layout -> g_qa
#pragma unroll
    for (int mt = 0; mt < 2; mt++)
#pragma unroll
        for (int nt = 0; nt < 4; nt++) {
            int row = m0 + wm + mt * 16 + (lane >> 2);
            int col = n0 + wn + nt * 8 + (lane & 3) * 2;
            *(float2*)&g_qa[row * Dd + col]       = make_float2(c[mt][nt][0], c[mt][nt][1]);
            *(float2*)&g_qa[(row + 8) * Dd + col] = make_float2(c[mt][nt][2], c[mt][nt][3]);
        }
}

// ================= K2: lut via 3xTF32 mma =================
// per m: cross = q[:, m*128:(m+1)*128] (1024x128) @ cb[m]^T (128x256)
// cb[m][c][j] is k-contiguous -> native col-major B for mma.row.col.
// lut[b][m*256+c] = csq[m*256+c] - 2*cross[b][c]
__global__ void __launch_bounds__(128) lut_mma(const float* __restrict__ cbk) {
    __shared__ unsigned Ah[64 * A_STRIDE], Al[64 * A_STRIDE];   // q tile   [row][k] pad 20
    __shared__ unsigned Ch[64 * A_STRIDE], Cl[64 * A_STRIDE];   // cb tile  [c][k]   pad 20
    int tid  = threadIdx.x;
    int lane = tid & 31;
    int w    = tid >> 5;
    int m  = blockIdx.z;
    int b0 = blockIdx.y * 64;
    int c0 = blockIdx.x * 64;
    int wm = (w & 1) * 32;
    int wn = (w >> 1) * 32;

    float c[2][4][4];
#pragma unroll
    for (int mt = 0; mt < 2; mt++)
#pragma unroll
        for (int nt = 0; nt < 4; nt++)
#pragma unroll
            for (int r = 0; r < 4; r++) c[mt][nt][r] = 0.f;

    int ar = tid >> 2, aq = (tid & 3) * 4;     // 32 rows/pass, 4 k-floats/thread
    const float* cbm = cbk + m * KS * DSs;

    for (int k0 = 0; k0 < DSs; k0 += 16) {
#pragma unroll
        for (int p = 0; p < 2; p++) {
            int r = ar + p * 32;
            // q rows
            float4 v = *(const float4*)&g_qa[(b0 + r) * Dd + m * DSs + k0 + aq];
            unsigned h0 = f2tf(v.x), h1 = f2tf(v.y), h2 = f2tf(v.z), h3 = f2tf(v.w);
            unsigned l0 = f2tf(v.x - __uint_as_float(h0));
            unsigned l1 = f2tf(v.y - __uint_as_float(h1));
            unsigned l2 = f2tf(v.z - __uint_as_float(h2));
            unsigned l3 = f2tf(v.w - __uint_as_float(h3));
            int base = r * A_STRIDE + aq;
            Ah[base + 0] = h0; Ah[base + 1] = h1; Ah[base + 2] = h2; Ah[base + 3] = h3;
            Al[base + 0] = l0; Al[base + 1] = l1; Al[base + 2] = l2; Al[base + 3] = l3;
            // codebook rows (c-major, k-contiguous)
            float4 u = *(const float4*)&cbm[(c0 + r) * DSs + k0 + aq];
            unsigned g0 = f2tf(u.x), g1 = f2tf(u.y), g2 = f2tf(u.z), g3 = f2tf(u.w);
            unsigned e0 = f2tf(u.x - __uint_as_float(g0));
            unsigned e1 = f2tf(u.y - __uint_as_float(g1));
            unsigned e2 = f2tf(u.z - __uint_as_float(g2));
            unsigned e3 = f2tf(u.w - __uint_as_float(g3));
            Ch[base + 0] = g0; Ch[base + 1] = g1; Ch[base + 2] = g2; Ch[base + 3] = g3;
            Cl[base + 0] = e0; Cl[base + 1] = e1; Cl[base + 2] = e2; Cl[base + 3] = e3;
        }
        __syncthreads();

#pragma unroll
        for (int ks = 0; ks < 2; ks++) {
            int kb = ks * 8;
            unsigned ah[2][4], al[2][4];
#pragma unroll
            for (int mt = 0; mt < 2; mt++) {
                int r0 = wm + mt * 16 + (lane >> 2);
                int k  = kb + (lane & 3);
                ah[mt][0] = Ah[ r0      * A_STRIDE + k    ];
                ah[mt][1] = Ah[(r0 + 8) * A_STRIDE + k    ];
                ah[mt][2] = Ah[ r0      * A_STRIDE + k + 4];
                ah[mt][3] = Ah[(r0 + 8) * A_STRIDE + k + 4];
                al[mt][0] = Al[ r0      * A_STRIDE + k    ];
                al[mt][1] = Al[(r0 + 8) * A_STRIDE + k    ];
                al[mt][2] = Al[ r0      * A_STRIDE + k + 4];
                al[mt][3] = Al[(r0 + 8) * A_STRIDE + k + 4];
            }
#pragma unroll
            for (int nt = 0; nt < 4; nt++) {
                int cc = wn + nt * 8 + (lane >> 2);
                int kr = kb + (lane & 3);
                unsigned bh0 = Ch[cc * A_STRIDE + kr    ];
                unsigned bh1 = Ch[cc * A_STRIDE + kr + 4];
                unsigned bl0 = Cl[cc * A_STRIDE + kr    ];
                unsigned bl1 = Cl[cc * A_STRIDE + kr + 4];
#pragma unroll
                for (int mt = 0; mt < 2; mt++) {
                    MMA_TF32(c[mt][nt], ah[mt], bh0, bh1);
                    MMA_TF32(c[mt][nt], ah[mt], bl0, bl1);
                    MMA_TF32(c[mt][nt], al[mt], bh0, bh1);
                }
            }
        }
        __syncthreads();
    }

    // epilogue: lut = csq - 2*cross
#pragma unroll
    for (int mt = 0; mt < 2; mt++)
#pragma unroll
        for (int nt = 0; nt < 4; nt++) {
            int row = b0 + wm + mt * 16 + (lane >> 2);
            int col = c0 + wn + nt * 8 + (lane & 3) * 2;
            float2 s = *(const float2*)&g_csq[m * KS + col];
            *(float2*)&g_lut[row * OUTn + m * KS + col] =
                make_float2(s.x - 2.f * c[mt][nt][0], s.y - 2.f * c[mt][nt][1]);
            *(float2*)&g_lut[(row + 8) * OUTn + m * KS + col] =
                make_float2(s.x - 2.f * c[mt][nt][2], s.y - 2.f * c[mt][nt][3]);
        }
}

// ================= register/shfl bitonic top-64 machinery =================
__device__ __forceinline__ void cx_shfl(float& v, int& i, int lane, int ehi, int k, int j) {
    float pv = __shfl_xor_sync(0xffffffffu, v, j);
    int   pi = __shfl_xor_sync(0xffffffffu, i, j);
    bool up = (((ehi + lane) & k) == 0);
    bool keep_min = (up == ((lane & j) == 0));
    if ((pv < v) == keep_min) { v = pv; i = pi; }
}

// full bitonic sort of 64 (ascending)
__device__ __forceinline__ void sort64(float& v0, int& i0, float& v1, int& i1, int lane) {
#pragma unroll
    for (int k = 2; k <= 32; k <<= 1) {
#pragma unroll
        for (int j = k >> 1; j >= 1; j >>= 1) {
            cx_shfl(v0, i0, lane, 0, k, j);
            cx_shfl(v1, i1, lane, 32, k, j);
        }
    }
    if (v1 < v0) { float t = v0; v0 = v1; v1 = t; int ti = i0; i0 = i1; i1 = ti; }
#pragma unroll
    for (int j = 16; j >= 1; j >>= 1) {
        cx_shfl(v0, i0, lane, 0, 64, j);
        cx_shfl(v1, i1, lane, 32, 64, j);
    }
}

// merge kept(asc) with batch(asc): kept <- smallest 64 of union, sorted ascending
__device__ __forceinline__ void merge64(float& k0v, int& k0i, float& k1v, int& k1i,
                                        float b0v, int b0i, float b1v, int b1i, int lane) {
    float r0v = __shfl_xor_sync(0xffffffffu, b1v, 31);
    int   r0i = __shfl_xor_sync(0xffffffffu, b1i, 31);
    float r1v = __shfl_xor_sync(0xffffffffu, b0v, 31);
    int   r1i = __shfl_xor_sync(0xffffffffu, b0i, 31);
    if (r0v < k0v) { k0v = r0v; k0i = r0i; }
    if (r1v < k1v) { k1v = r1v; k1i = r1i; }
    if (k1v < k0v) { float t = k0v; k0v = k1v; k1v = t; int ti = k0i; k0i = k1i; k1i = ti; }
#pragma unroll
    for (int j = 16; j >= 1; j >>= 1) {
        cx_shfl(k0v, k0i, lane, 0, 64, j);
        cx_shfl(k1v, k1i, lane, 32, 64, j);
    }
}

// ---------------- K3: warp-autonomous PQ scan, register top-64 (R11) ----------------
__global__ void __launch_bounds__(512, 4) scan_k(const int* __restrict__ vcodes,
                                                 const float* __restrict__ vcb,
                                                 const float* __restrict__ bias,
                                                 float* __restrict__ out) {
    int b = blockIdx.x;
    int tid = threadIdx.x;
    int lane = tid & 31;
    int w = tid >> 5;                  // 16 warps
    __shared__ float lut_s[2048];      // 8 KB
    __shared__ float bufd[16 * 96];    // 6 KB : per-warp candidate buffer / kept lists
    __shared__ int   bufi[16 * 96];    // 6 KB
    __shared__ float s_w[KTOP];
    __shared__ float s_winv;

    // stage LUT (8 KB)
    ((float4*)lut_s)[tid] = ((const float4*)&g_lut[b * 2048])[tid];
    __syncthreads();

    float* mbd = bufd + w * 96;
    int*   mbi = bufi + w * 96;
    int   cnt = 0;
    float tau = FLT_MAX;
    float k0v = FLT_MAX, k1v = FLT_MAX;   // kept top-64 (registers, sorted asc)
    int   k0i = 0, k1i = 0;
    unsigned lanemask_lt = (1u << lane) - 1u;

    int nbase = w << 12;               // warp stripe: 4096 codes
    unsigned long long c8 = g_codes[nbase + lane];
#pragma unroll 1
    for (int it = 0; it < 128; ++it) {
        int n = nbase + (it << 5) + lane;
        unsigned long long nx = (it < 127) ? g_codes[n + 32] : 0ULL;
        unsigned lo = (unsigned)c8;
        unsigned hi = (unsigned)(c8 >> 32);
        float t0 = lut_s[          (lo         & 255u)];
        float t1 = lut_s[ 256 + ((lo >>  8) & 255u)];
        float t2 = lut_s[ 512 + ((lo >> 16) & 255u)];
        float t3 = lut_s[ 768 +  (lo >> 24)         ];
        float t4 = lut_s[1024 + ( hi         & 255u)];
        float t5 = lut_s[1280 + ((hi >>  8) & 255u)];
        float t6 = lut_s[1536 + ((hi >> 16) & 255u)];
        float t7 = lut_s[1792 +  (hi >> 24)         ];
        float d = ((t0 + t1) + (t2 + t3)) + ((t4 + t5) + (t6 + t7));
        c8 = nx;
        unsigned ball = __ballot_sync(0xffffffffu, d < tau);
        if (d < tau) {
            int pos = cnt + __popc(ball & lanemask_lt);
            mbd[pos] = d; mbi[pos] = n;
        }
        cnt += __popc(ball);
        if (cnt >= 64) {                    // flush: sort batch of 64, merge into kept
            __syncwarp();
            float b0v = mbd[lane], b1v = mbd[32 + lane];
            int   b0i = mbi[lane], b1i = mbi[32 + lane];
            int left = cnt - 64;
            if (lane < left) { mbd[lane] = mbd[64 + lane]; mbi[lane] = mbi[64 + lane]; }
            cnt = left;
            __syncwarp();
            sort64(b0v, b0i, b1v, b1i, lane);
            merge64(k0v, k0i, k1v, k1i, b0v, b0i, b1v, b1i, lane);
            tau = __shfl_sync(0xffffffffu, k1v, 31);
        }
    }
    // final partial flush
    if (cnt > 0) {
        for (int i2 = cnt + lane; i2 < 64; i2 += 32) mbd[i2] = FLT_MAX;
        __syncwarp();
        float b0v = mbd[lane], b1v = mbd[32 + lane];
        int   b0i = mbi[lane], b1i = mbi[32 + lane];
        sort64(b0v, b0i, b1v, b1i, lane);
        merge64(k0v, k0i, k1v, k1i, b0v, b0i, b1v, b1i, lane);
    }
    // publish warp's sorted top-64
    mbd[lane] = k0v;  mbd[32 + lane] = k1v;
    mbi[lane] = k0i;  mbi[32 + lane] = k1i;
    __syncthreads();

    // tournament merge of 16 sorted lists (4 rounds, register merges)
#pragma unroll
    for (int step = 1; step < 16; step <<= 1) {
        if (w * 2 * step < 16) {
            int ia = w * 2 * step, ib = ia + step;
            float a0 = bufd[ia * 96 + lane],      a1 = bufd[ia * 96 + 32 + lane];
            int   x0 = bufi[ia * 96 + lane],      x1 = bufi[ia * 96 + 32 + lane];
            float c0 = bufd[ib * 96 + lane],      c1 = bufd[ib * 96 + 32 + lane];
            int   y0 = bufi[ib * 96 + lane],      y1 = bufi[ib * 96 + 32 + lane];
            merge64(a0, x0, a1, x1, c0, y0, c1, y1, lane);
            bufd[ia * 96 + lane] = a0;  bufd[ia * 96 + 32 + lane] = a1;
            bufi[ia * 96 + lane] = x0;  bufi[ia * 96 + 32 + lane] = x1;
        }
        __syncthreads();
    }
    // final top-64 sorted ascending at bufd[0..63] / bufi[0..63]

    // softmax over -dist (q_sq shift cancels; shift by best dist)
    float d0 = bufd[0];
    if (tid < KTOP) s_w[tid] = expf(d0 - bufd[tid]);
    __syncthreads();
    if (tid == 0) {
        float s = 0.f;
        for (int i = 0; i < KTOP; i++) s += s_w[i];
        s_winv = 1.0f / s;
    }
    __syncthreads();

    // y[b, o] = bias[o] + sum_k w_k * vcb[mv][value_codes[n_k][mv]][dv]
    int o0   = tid << 2;          // 4 outputs per thread (512*4 = 2048)
    int mv   = tid >> 6;          // warp-uniform
    int col4 = (o0 & 255) >> 2;
    float4 acc = *(const float4*)&bias[o0];
    const float4* vcb4 = (const float4*)vcb;
    float winv = s_winv;
#pragma unroll 4
    for (int kk = 0; kk < KTOP; kk++) {
        int n = bufi[kk];
        float wt = s_w[kk] * winv;
        int code = vcodes[n * 8 + mv];
        float4 v = vcb4[(((mv << 8) + code) << 6) + col4];
        acc.x = fmaf(wt, v.x, acc.x);
        acc.y = fmaf(wt, v.y, acc.y);
        acc.z = fmaf(wt, v.z, acc.z);
        acc.w = fmaf(wt, v.w, acc.w);
    }
    *(float4*)&out[b * OUTn + o0] = acc;
}

// ---------------- launch ----------------
extern "C" void kernel_launch(void* const* d_in, const int* in_sizes, int n_in,
                              void* d_out, int out_size) {
    const float* x    = (const float*)d_in[0];   // (B, D)
    const float* W    = (const float*)d_in[1];   // (D, D)
    const float* kcb  = (const float*)d_in[2];   // (M, Ks, DS)
    const float* vcb  = (const float*)d_in[3];   // (MV, Ks, DV)
    const float* bias = (const float*)d_in[4];   // (OUT,)
    const int*   kc   = (const int*)d_in[5];     // (N, M)
    const int*   vc   = (const int*)d_in[6];     // (N, MV)
    float* out = (float*)d_out;                  // (B, OUT)

    pack_codes_k<<<Nn / 256, 256>>>(kc);
    csq_k<<<(Mm * KS * 32) / 256, 256>>>(kcb);
    gemm_tc<<<dim3(Dd / 64, Bq / 64), 128>>>(x, W);
    lut_mma<<<dim3(KS / 64, Bq / 64, Mm), 128>>>(kcb);
    scan_k<<<Bq, 512>>>(vc, vcb, bias, out);
}